// round 16
// baseline (speedup 1.0000x reference)
#include <cuda_runtime.h>
#include <cuda_bf16.h>
#include <cuda_fp16.h>
#include <cstdint>

namespace {
constexpr int B  = 2;
constexpr int S  = 2048;
constexpr int H  = 16;
constexpr int D  = 64;
constexpr int TQ = 64;
constexpr int TK = 64;
constexpr int NT = 128;   // 4 warps
constexpr int HD = H * D;
constexpr int NTILES = S / TK;     // 32
constexpr int TILE_BYTES = 64 * 128;
constexpr int BUF = 24576;          // KH 0, KL 8K, VH 16K
constexpr int SMEM_BYTES = 2 * BUF; // 48KB
constexpr float LOG2E = 1.4426950408889634f;
constexpr int SPLIT_BLOCKS = (B * H * S * 16) / 256;          // 4096
constexpr int MASK_BLOCKS  = (B * S * NTILES * 32) / 256;     // 16384
}

// Pre-split, pre-swizzled tiles: K = bf16 hi/lo, V = fp16 single. [bh][tile] 8KB blocks.
__device__ __align__(16) unsigned char gKH[(size_t)B * H * NTILES * TILE_BYTES];
__device__ __align__(16) unsigned char gKL[(size_t)B * H * NTILES * TILE_BYTES];
__device__ __align__(16) unsigned char gVH[(size_t)B * H * NTILES * TILE_BYTES];
// Packed mask: [B*S][NTILES] uint64
__device__ __align__(16) unsigned long long gPM[(size_t)B * S * NTILES];

__device__ __forceinline__ uint32_t swz(uint32_t off) { return off ^ ((off >> 3) & 0x70); }

__device__ __forceinline__ void cpasync16(uint32_t dst, const void* src) {
    asm volatile("cp.async.cg.shared.global [%0], [%1], 16;" :: "r"(dst), "l"(src));
}
__device__ __forceinline__ void ldsm4(uint32_t& r0, uint32_t& r1, uint32_t& r2, uint32_t& r3, uint32_t a) {
    asm volatile("ldmatrix.sync.aligned.m8n8.x4.shared.b16 {%0,%1,%2,%3},[%4];"
                 : "=r"(r0), "=r"(r1), "=r"(r2), "=r"(r3) : "r"(a));
}
__device__ __forceinline__ void ldsm4t(uint32_t& r0, uint32_t& r1, uint32_t& r2, uint32_t& r3, uint32_t a) {
    asm volatile("ldmatrix.sync.aligned.m8n8.x4.trans.shared.b16 {%0,%1,%2,%3},[%4];"
                 : "=r"(r0), "=r"(r1), "=r"(r2), "=r"(r3) : "r"(a));
}
// bf16 MMA (QK path)
__device__ __forceinline__ void mma_bf(float c[4], uint32_t a0, uint32_t a1, uint32_t a2, uint32_t a3,
                                       uint32_t b0, uint32_t b1) {
    asm volatile("mma.sync.aligned.m16n8k16.row.col.f32.bf16.bf16.f32 "
                 "{%0,%1,%2,%3},{%4,%5,%6,%7},{%8,%9},{%0,%1,%2,%3};"
                 : "+f"(c[0]), "+f"(c[1]), "+f"(c[2]), "+f"(c[3])
                 : "r"(a0), "r"(a1), "r"(a2), "r"(a3), "r"(b0), "r"(b1));
}
// fp16 MMA (PV path)
__device__ __forceinline__ void mma_fp(float c[4], uint32_t a0, uint32_t a1, uint32_t a2, uint32_t a3,
                                       uint32_t b0, uint32_t b1) {
    asm volatile("mma.sync.aligned.m16n8k16.row.col.f32.f16.f16.f32 "
                 "{%0,%1,%2,%3},{%4,%5,%6,%7},{%8,%9},{%0,%1,%2,%3};"
                 : "+f"(c[0]), "+f"(c[1]), "+f"(c[2]), "+f"(c[3])
                 : "r"(a0), "r"(a1), "r"(a2), "r"(a3), "r"(b0), "r"(b1));
}
__device__ __forceinline__ float ex2(float x) {
    float y; asm("ex2.approx.f32 %0, %1;" : "=f"(y) : "f"(x)); return y;
}
// packed f16x2: first src -> high half
__device__ __forceinline__ uint32_t cvt_f16x2(float hi, float lo) {
    uint32_t r; asm("cvt.rn.f16x2.f32 %0, %1, %2;" : "=r"(r) : "f"(hi), "f"(lo)); return r;
}
__device__ __forceinline__ uint32_t pack_bf(float x, float y) {
    __nv_bfloat16 hx = __float2bfloat16_rn(x), hy = __float2bfloat16_rn(y);
    return (uint32_t)__bfloat16_as_ushort(hx) | ((uint32_t)__bfloat16_as_ushort(hy) << 16);
}
// bf16 hi/lo split (Q, K)
__device__ __forceinline__ void split4(float4 t, uint2& hv, uint2& lv) {
    __nv_bfloat16 h0 = __float2bfloat16_rn(t.x), h1 = __float2bfloat16_rn(t.y);
    __nv_bfloat16 h2 = __float2bfloat16_rn(t.z), h3 = __float2bfloat16_rn(t.w);
    hv.x = (uint32_t)__bfloat16_as_ushort(h0) | ((uint32_t)__bfloat16_as_ushort(h1) << 16);
    hv.y = (uint32_t)__bfloat16_as_ushort(h2) | ((uint32_t)__bfloat16_as_ushort(h3) << 16);
    lv.x = pack_bf(t.x - __bfloat162float(h0), t.y - __bfloat162float(h1));
    lv.y = pack_bf(t.z - __bfloat162float(h2), t.w - __bfloat162float(h3));
}

// ---- fused prepass: blocks [0, SPLIT_BLOCKS) split K/V; the rest pack the mask ----
__global__ void __launch_bounds__(256)
prepass_kernel(const float* __restrict__ gk, const float* __restrict__ gv,
               const int* __restrict__ gmask)
{
    if (blockIdx.x < SPLIT_BLOCKS) {
        const int idx = blockIdx.x * 256 + threadIdx.x;
        const int c16 = idx & 15;
        const int s   = (idx >> 4) & (S - 1);
        const int bh  = idx >> 15;
        const int b = bh >> 4, h = bh & 15;

        const size_t gsrc = ((size_t)(b * S + s) * H + h) * D + c16 * 4;
        const float4 kt = *reinterpret_cast<const float4*>(gk + gsrc);
        const float4 vt = *reinterpret_cast<const float4*>(gv + gsrc);

        const size_t base = ((size_t)(bh * NTILES + (s >> 6)) << 13)
                          + swz((uint32_t)((s & 63) * 128 + c16 * 8));
        uint2 hv, lv;
        split4(kt, hv, lv);
        *reinterpret_cast<uint2*>(gKH + base) = hv;
        *reinterpret_cast<uint2*>(gKL + base) = lv;
        uint2 vv;
        vv.x = cvt_f16x2(vt.y, vt.x);
        vv.y = cvt_f16x2(vt.w, vt.z);
        *reinterpret_cast<uint2*>(gVH + base) = vv;
    } else {
        const int idx2 = (blockIdx.x - SPLIT_BLOCKS) * 256 + threadIdx.x;
        const int gw   = idx2 >> 5;          // [0, B*S*NTILES)
        const int lane = threadIdx.x & 31;
        const int row   = gw >> 5;           // 0..B*S-1
        const int chunk = gw & 31;
        const int* mr = gmask + (size_t)row * S + chunk * 64;
        const unsigned lo = __ballot_sync(0xffffffffu, mr[lane]      != 0);
        const unsigned hi = __ballot_sync(0xffffffffu, mr[lane + 32] != 0);
        if (lane == 0)
            gPM[(size_t)row * NTILES + chunk] = ((unsigned long long)hi << 32) | lo;
    }
}

__device__ __forceinline__ void copy_tile(uint32_t dst, const size_t tb, int tid) {
    #pragma unroll
    for (int r = 0; r < 4; r++) {
        const int off = r * 2048 + tid * 16;
        cpasync16(dst + off,         gKH + tb + off);
        cpasync16(dst + 8192 + off,  gKL + tb + off);
        cpasync16(dst + 16384 + off, gVH + tb + off);
    }
}

__global__ void __launch_bounds__(NT, 3)
attn_mma_kernel(const float* __restrict__ gq, const float* __restrict__ gbias,
                float* __restrict__ gout)
{
    extern __shared__ char smem[];
    const uint32_t smu = (uint32_t)__cvta_generic_to_shared(smem);

    const int tid  = threadIdx.x;
    const int lane = tid & 31;
    const int w    = tid >> 5;
    const int bh   = blockIdx.x;
    const int b    = bh >> 4;
    const int h    = bh & 15;
    const int q0   = blockIdx.y * TQ;

    const int sub = lane >> 3, lr = lane & 7;
    const int a_row = 16 * w + lr + ((sub & 1) << 3);
    const int a_ca  = sub >> 1;
    const int b_ro  = lr + ((sub >> 1) << 3);
    const int b_ca  = sub & 1;
    const int v_ro  = lr + ((sub & 1) << 3);
    const int v_ca  = sub >> 1;

    const size_t tile_base0 = (size_t)(bh * NTILES) << 13;

    // tile0 copy into buf0 (overlaps Q staging)
    copy_tile(smu, tile_base0, tid);
    asm volatile("cp.async.commit_group;");

    // ---- stage Q (x 8*log2e, bf16 split) into buf1, take register fragments ----
    {
        const float* qb = gq + ((size_t)(b * S + q0) * H + h) * D;
        const float qs = 8.0f * LOG2E;
        #pragma unroll
        for (int r = 0; r < 8; r++) {
            const int idx = r * NT + tid;
            const int row = idx >> 4, c16 = idx & 15;
            float4 t = *reinterpret_cast<const float4*>(qb + (size_t)row * HD + c16 * 4);
            t.x *= qs; t.y *= qs; t.z *= qs; t.w *= qs;
            uint2 hv, lv;
            split4(t, hv, lv);
            const uint32_t so = swz((uint32_t)(row * 128 + c16 * 8));
            *reinterpret_cast<uint2*>(smem + BUF + so)        = hv;
            *reinterpret_cast<uint2*>(smem + BUF + 8192 + so) = lv;
        }
    }
    __syncthreads();

    uint32_t qh[4][4], ql[4][4];
    #pragma unroll
    for (int ks = 0; ks < 4; ks++) {
        const uint32_t off = swz((uint32_t)(a_row * 128 + (2 * ks + a_ca) * 16));
        ldsm4(qh[ks][0], qh[ks][1], qh[ks][2], qh[ks][3], smu + BUF + off);
        ldsm4(ql[ks][0], ql[ks][1], ql[ks][2], ql[ks][3], smu + BUF + 8192 + off);
    }
    __syncthreads();

    // tile1 copy into buf1
    copy_tile(smu + BUF, tile_base0 + TILE_BYTES, tid);
    asm volatile("cp.async.commit_group;");

    float ofr[8][4];
    #pragma unroll
    for (int j = 0; j < 8; j++)
        #pragma unroll
        for (int e = 0; e < 4; e++) ofr[j][e] = 0.f;
    float mrow[2] = {-1e30f, -1e30f};   // log2-domain running max
    float lrow[2] = {0.f, 0.f};

    const int rr0 = q0 + 16 * w + (lane >> 2);
    const int cq  = (lane & 3) * 2;
    const unsigned long long* pm0 = gPM + (size_t)(b * S + rr0) * NTILES;
    const unsigned long long* pm1 = gPM + (size_t)(b * S + rr0 + 8) * NTILES;

    for (int it = 0; it < NTILES; it++) {
        const int k0 = it * TK;
        const uint32_t bufb = (uint32_t)(it & 1) * BUF;
        const uint32_t KHI = bufb, KLO = bufb + 8192, VHI = bufb + 16384;

        // ---- hoisted: mask + bias loads issued BEFORE the cp.async wait/barrier,
        //      so their DRAM latency overlaps the stall instead of following it ----
        const unsigned long long mw[2] = {pm0[it], pm1[it]};
        float2 bfr0[4][2], bfr1[4][2];
        #pragma unroll
        for (int j = 0; j < 4; j++)
            #pragma unroll
            for (int p = 0; p < 2; p++) {
                const float* brow = gbias + ((size_t)bh * S + rr0 + 8 * p) * S + k0;
                bfr0[j][p] = *reinterpret_cast<const float2*>(brow + 8 * j + cq);
                bfr1[j][p] = *reinterpret_cast<const float2*>(brow + 32 + 8 * j + cq);
            }

        asm volatile("cp.async.wait_group 1;");
        __syncthreads();

        float sfr[8][4];
        #pragma unroll
        for (int j = 0; j < 8; j++)
            #pragma unroll
            for (int e = 0; e < 4; e++) sfr[j][e] = 0.f;

        // ---- QK: bf16 3-term, all 64 keys ----
        #pragma unroll
        for (int ks = 0; ks < 4; ks++)
            #pragma unroll
            for (int i = 0; i < 4; i++) {
                const uint32_t off = swz((uint32_t)((16 * i + b_ro) * 128 + (2 * ks + b_ca) * 16));
                uint32_t kh0, kh1, kh2, kh3, kl0, kl1, kl2, kl3;
                ldsm4(kh0, kh1, kh2, kh3, smu + KHI + off);
                ldsm4(kl0, kl1, kl2, kl3, smu + KLO + off);
                mma_bf(sfr[2 * i],     qh[ks][0], qh[ks][1], qh[ks][2], qh[ks][3], kh0, kh1);
                mma_bf(sfr[2 * i],     qh[ks][0], qh[ks][1], qh[ks][2], qh[ks][3], kl0, kl1);
                mma_bf(sfr[2 * i],     ql[ks][0], ql[ks][1], ql[ks][2], ql[ks][3], kh0, kh1);
                mma_bf(sfr[2 * i + 1], qh[ks][0], qh[ks][1], qh[ks][2], qh[ks][3], kh2, kh3);
                mma_bf(sfr[2 * i + 1], qh[ks][0], qh[ks][1], qh[ks][2], qh[ks][3], kl2, kl3);
                mma_bf(sfr[2 * i + 1], ql[ks][0], ql[ks][1], ql[ks][2], ql[ks][3], kh2, kh3);
            }

        // ---- bias (x log2e via FMA) + packed mask ----
        #pragma unroll
        for (int j = 0; j < 8; j++) {
            const float2* bp = (j < 4) ? bfr0[j] : bfr1[j - 4];
            const int base = 8 * j + cq;
            #pragma unroll
            for (int p = 0; p < 2; p++) {
                const unsigned mb = (unsigned)(mw[p] >> base);
                sfr[j][2 * p]     = (mb & 1u) ? 0.0f : fmaf(bp[p].x, LOG2E, sfr[j][2 * p]);
                sfr[j][2 * p + 1] = (mb & 2u) ? 0.0f : fmaf(bp[p].y, LOG2E, sfr[j][2 * p + 1]);
            }
        }

        // ---- single online softmax (log2 domain, EX2 only) ----
        float mold[2], mnew2[2], rs2[2];
        #pragma unroll
        for (int p = 0; p < 2; p++) {
            float mx = -1e30f;
            #pragma unroll
            for (int j = 0; j < 8; j++)
                mx = fmaxf(mx, fmaxf(sfr[j][2 * p], sfr[j][2 * p + 1]));
            mx = fmaxf(mx, __shfl_xor_sync(0xffffffffu, mx, 1));
            mx = fmaxf(mx, __shfl_xor_sync(0xffffffffu, mx, 2));
            mold[p] = mrow[p];
            const float mnew = fmaxf(mrow[p], mx);
            mrow[p] = mnew;
            mnew2[p] = mnew;

            float rs = 0.f;
            #pragma unroll
            for (int j = 0; j < 8; j++) {
                const float e0 = ex2(sfr[j][2 * p]     - mnew);
                const float e1 = ex2(sfr[j][2 * p + 1] - mnew);
                sfr[j][2 * p] = e0; sfr[j][2 * p + 1] = e1;
                rs += e0 + e1;
            }
            rs += __shfl_xor_sync(0xffffffffu, rs, 1);
            rs += __shfl_xor_sync(0xffffffffu, rs, 2);
            rs2[p] = rs;
        }

        // lazy rescale (warp-uniform skip)
        const bool moved = (mnew2[0] != mold[0]) || (mnew2[1] != mold[1]);
        if (__any_sync(0xffffffffu, moved)) {
            const float c0 = ex2(mold[0] - mnew2[0]);
            const float c1 = ex2(mold[1] - mnew2[1]);
            lrow[0] = lrow[0] * c0 + rs2[0];
            lrow[1] = lrow[1] * c1 + rs2[1];
            #pragma unroll
            for (int j = 0; j < 8; j++) {
                ofr[j][0] *= c0; ofr[j][1] *= c0;
                ofr[j][2] *= c1; ofr[j][3] *= c1;
            }
        } else {
            lrow[0] += rs2[0];
            lrow[1] += rs2[1];
        }

        // ---- PV: fp16 1-term (P single fp16, V single fp16) ----
        #pragma unroll
        for (int ksp = 0; ksp < 4; ksp++) {
            uint32_t ph[4];
            #pragma unroll
            for (int half = 0; half < 2; half++) {
                const int j = 2 * ksp + half;
                #pragma unroll
                for (int p = 0; p < 2; p++)
                    ph[half * 2 + p] = cvt_f16x2(sfr[j][2 * p + 1], sfr[j][2 * p]);
            }
            #pragma unroll
            for (int i = 0; i < 4; i++) {
                const uint32_t off = swz((uint32_t)((16 * ksp + v_ro) * 128 + (2 * i + v_ca) * 16));
                uint32_t vh0, vh1, vh2, vh3;
                ldsm4t(vh0, vh1, vh2, vh3, smu + VHI + off);
                mma_fp(ofr[2 * i],     ph[0], ph[1], ph[2], ph[3], vh0, vh1);
                mma_fp(ofr[2 * i + 1], ph[0], ph[1], ph[2], ph[3], vh2, vh3);
            }
        }

        __syncthreads();
        if (it + 2 < NTILES)
            copy_tile(smu + bufb, tile_base0 + (size_t)(it + 2) * TILE_BYTES, tid);
        asm volatile("cp.async.commit_group;");
    }

    // ---- epilogue ----
    const float inv0 = 1.0f / lrow[0];
    const float inv1 = 1.0f / lrow[1];
    #pragma unroll
    for (int j = 0; j < 8; j++) {
        const int d = 8 * j + cq;
        float2 w0 = make_float2(ofr[j][0] * inv0, ofr[j][1] * inv0);
        float2 w1 = make_float2(ofr[j][2] * inv1, ofr[j][3] * inv1);
        *reinterpret_cast<float2*>(gout + ((size_t)(b * S + rr0)     * H + h) * D + d) = w0;
        *reinterpret_cast<float2*>(gout + ((size_t)(b * S + rr0 + 8) * H + h) * D + d) = w1;
    }
}

extern "C" void kernel_launch(void* const* d_in, const int* in_sizes, int n_in,
                              void* d_out, int out_size) {
    const float* q    = (const float*)d_in[0];
    const float* k    = (const float*)d_in[1];
    const float* v    = (const float*)d_in[2];
    const float* bias = (const float*)d_in[3];
    const int*   mask = (const int*)d_in[4];
    float* out = (float*)d_out;

    prepass_kernel<<<SPLIT_BLOCKS + MASK_BLOCKS, 256>>>(k, v, mask);

    cudaFuncSetAttribute(attn_mma_kernel,
                         cudaFuncAttributeMaxDynamicSharedMemorySize, SMEM_BYTES);
    dim3 grid(B * H, S / TQ);
    attn_mma_kernel<<<grid, NT, SMEM_BYTES>>>(q, bias, out);
}

// round 17
// speedup vs baseline: 1.1330x; 1.1330x over previous
#include <cuda_runtime.h>
#include <cuda_bf16.h>
#include <cuda_fp16.h>
#include <cstdint>

namespace {
constexpr int B  = 2;
constexpr int S  = 2048;
constexpr int H  = 16;
constexpr int D  = 64;
constexpr int TQ = 64;
constexpr int TK = 64;
constexpr int NT = 128;   // 4 warps
constexpr int HD = H * D;
constexpr int NTILES = S / TK;     // 32
constexpr int TILE_BYTES = 64 * 128;
constexpr int BUF = 24576;          // KH 0, KL 8K, VH 16K
constexpr int SMEM_BYTES = 2 * BUF; // 48KB
constexpr float LOG2E = 1.4426950408889634f;
constexpr int SPLIT_BLOCKS = (B * H * S * 16) / 256;          // 4096
constexpr int MASK_BLOCKS  = (B * S * NTILES * 32) / 256;     // 16384
}

// Pre-split, pre-swizzled tiles: K = bf16 hi/lo, V = fp16 single. [bh][tile] 8KB blocks.
__device__ __align__(16) unsigned char gKH[(size_t)B * H * NTILES * TILE_BYTES];
__device__ __align__(16) unsigned char gKL[(size_t)B * H * NTILES * TILE_BYTES];
__device__ __align__(16) unsigned char gVH[(size_t)B * H * NTILES * TILE_BYTES];
// Packed mask: [B*S][NTILES] uint64
__device__ __align__(16) unsigned long long gPM[(size_t)B * S * NTILES];

__device__ __forceinline__ uint32_t swz(uint32_t off) { return off ^ ((off >> 3) & 0x70); }

__device__ __forceinline__ void cpasync16(uint32_t dst, const void* src) {
    asm volatile("cp.async.cg.shared.global [%0], [%1], 16;" :: "r"(dst), "l"(src));
}
__device__ __forceinline__ void ldsm4(uint32_t& r0, uint32_t& r1, uint32_t& r2, uint32_t& r3, uint32_t a) {
    asm volatile("ldmatrix.sync.aligned.m8n8.x4.shared.b16 {%0,%1,%2,%3},[%4];"
                 : "=r"(r0), "=r"(r1), "=r"(r2), "=r"(r3) : "r"(a));
}
__device__ __forceinline__ void ldsm4t(uint32_t& r0, uint32_t& r1, uint32_t& r2, uint32_t& r3, uint32_t a) {
    asm volatile("ldmatrix.sync.aligned.m8n8.x4.trans.shared.b16 {%0,%1,%2,%3},[%4];"
                 : "=r"(r0), "=r"(r1), "=r"(r2), "=r"(r3) : "r"(a));
}
// bf16 MMA (QK path)
__device__ __forceinline__ void mma_bf(float c[4], uint32_t a0, uint32_t a1, uint32_t a2, uint32_t a3,
                                       uint32_t b0, uint32_t b1) {
    asm volatile("mma.sync.aligned.m16n8k16.row.col.f32.bf16.bf16.f32 "
                 "{%0,%1,%2,%3},{%4,%5,%6,%7},{%8,%9},{%0,%1,%2,%3};"
                 : "+f"(c[0]), "+f"(c[1]), "+f"(c[2]), "+f"(c[3])
                 : "r"(a0), "r"(a1), "r"(a2), "r"(a3), "r"(b0), "r"(b1));
}
// fp16 MMA (PV path)
__device__ __forceinline__ void mma_fp(float c[4], uint32_t a0, uint32_t a1, uint32_t a2, uint32_t a3,
                                       uint32_t b0, uint32_t b1) {
    asm volatile("mma.sync.aligned.m16n8k16.row.col.f32.f16.f16.f32 "
                 "{%0,%1,%2,%3},{%4,%5,%6,%7},{%8,%9},{%0,%1,%2,%3};"
                 : "+f"(c[0]), "+f"(c[1]), "+f"(c[2]), "+f"(c[3])
                 : "r"(a0), "r"(a1), "r"(a2), "r"(a3), "r"(b0), "r"(b1));
}
__device__ __forceinline__ float ex2(float x) {
    float y; asm("ex2.approx.f32 %0, %1;" : "=f"(y) : "f"(x)); return y;
}
// packed f16x2: first src -> high half
__device__ __forceinline__ uint32_t cvt_f16x2(float hi, float lo) {
    uint32_t r; asm("cvt.rn.f16x2.f32 %0, %1, %2;" : "=r"(r) : "f"(hi), "f"(lo)); return r;
}
__device__ __forceinline__ uint32_t pack_bf(float x, float y) {
    __nv_bfloat16 hx = __float2bfloat16_rn(x), hy = __float2bfloat16_rn(y);
    return (uint32_t)__bfloat16_as_ushort(hx) | ((uint32_t)__bfloat16_as_ushort(hy) << 16);
}
// bf16 hi/lo split (Q, K)
__device__ __forceinline__ void split4(float4 t, uint2& hv, uint2& lv) {
    __nv_bfloat16 h0 = __float2bfloat16_rn(t.x), h1 = __float2bfloat16_rn(t.y);
    __nv_bfloat16 h2 = __float2bfloat16_rn(t.z), h3 = __float2bfloat16_rn(t.w);
    hv.x = (uint32_t)__bfloat16_as_ushort(h0) | ((uint32_t)__bfloat16_as_ushort(h1) << 16);
    hv.y = (uint32_t)__bfloat16_as_ushort(h2) | ((uint32_t)__bfloat16_as_ushort(h3) << 16);
    lv.x = pack_bf(t.x - __bfloat162float(h0), t.y - __bfloat162float(h1));
    lv.y = pack_bf(t.z - __bfloat162float(h2), t.w - __bfloat162float(h3));
}

// ---- fused prepass: blocks [0, SPLIT_BLOCKS) split K/V; the rest pack the mask ----
__global__ void __launch_bounds__(256)
prepass_kernel(const float* __restrict__ gk, const float* __restrict__ gv,
               const int* __restrict__ gmask)
{
    if (blockIdx.x < SPLIT_BLOCKS) {
        const int idx = blockIdx.x * 256 + threadIdx.x;
        const int c16 = idx & 15;
        const int s   = (idx >> 4) & (S - 1);
        const int bh  = idx >> 15;
        const int b = bh >> 4, h = bh & 15;

        const size_t gsrc = ((size_t)(b * S + s) * H + h) * D + c16 * 4;
        const float4 kt = *reinterpret_cast<const float4*>(gk + gsrc);
        const float4 vt = *reinterpret_cast<const float4*>(gv + gsrc);

        const size_t base = ((size_t)(bh * NTILES + (s >> 6)) << 13)
                          + swz((uint32_t)((s & 63) * 128 + c16 * 8));
        uint2 hv, lv;
        split4(kt, hv, lv);
        *reinterpret_cast<uint2*>(gKH + base) = hv;
        *reinterpret_cast<uint2*>(gKL + base) = lv;
        uint2 vv;
        vv.x = cvt_f16x2(vt.y, vt.x);
        vv.y = cvt_f16x2(vt.w, vt.z);
        *reinterpret_cast<uint2*>(gVH + base) = vv;
    } else {
        const int idx2 = (blockIdx.x - SPLIT_BLOCKS) * 256 + threadIdx.x;
        const int gw   = idx2 >> 5;          // [0, B*S*NTILES)
        const int lane = threadIdx.x & 31;
        const int row   = gw >> 5;           // 0..B*S-1
        const int chunk = gw & 31;
        const int* mr = gmask + (size_t)row * S + chunk * 64;
        const unsigned lo = __ballot_sync(0xffffffffu, mr[lane]      != 0);
        const unsigned hi = __ballot_sync(0xffffffffu, mr[lane + 32] != 0);
        if (lane == 0)
            gPM[(size_t)row * NTILES + chunk] = ((unsigned long long)hi << 32) | lo;
    }
}

__device__ __forceinline__ void copy_tile(uint32_t dst, const size_t tb, int tid) {
    #pragma unroll
    for (int r = 0; r < 4; r++) {
        const int off = r * 2048 + tid * 16;
        cpasync16(dst + off,         gKH + tb + off);
        cpasync16(dst + 8192 + off,  gKL + tb + off);
        cpasync16(dst + 16384 + off, gVH + tb + off);
    }
}

__global__ void __launch_bounds__(NT, 3)
attn_mma_kernel(const float* __restrict__ gq, const float* __restrict__ gbias,
                float* __restrict__ gout)
{
    extern __shared__ char smem[];
    const uint32_t smu = (uint32_t)__cvta_generic_to_shared(smem);

    const int tid  = threadIdx.x;
    const int lane = tid & 31;
    const int w    = tid >> 5;
    const int bh   = blockIdx.x;
    const int b    = bh >> 4;
    const int h    = bh & 15;
    const int q0   = blockIdx.y * TQ;

    const int sub = lane >> 3, lr = lane & 7;
    const int a_row = 16 * w + lr + ((sub & 1) << 3);
    const int a_ca  = sub >> 1;
    const int b_ro  = lr + ((sub >> 1) << 3);
    const int b_ca  = sub & 1;
    const int v_ro  = lr + ((sub & 1) << 3);
    const int v_ca  = sub >> 1;

    const size_t tile_base0 = (size_t)(bh * NTILES) << 13;

    // tile0 copy into buf0 (overlaps Q staging)
    copy_tile(smu, tile_base0, tid);
    asm volatile("cp.async.commit_group;");

    // ---- stage Q (x 8*log2e, bf16 split) into buf1, take register fragments ----
    {
        const float* qb = gq + ((size_t)(b * S + q0) * H + h) * D;
        const float qs = 8.0f * LOG2E;
        #pragma unroll
        for (int r = 0; r < 8; r++) {
            const int idx = r * NT + tid;
            const int row = idx >> 4, c16 = idx & 15;
            float4 t = *reinterpret_cast<const float4*>(qb + (size_t)row * HD + c16 * 4);
            t.x *= qs; t.y *= qs; t.z *= qs; t.w *= qs;
            uint2 hv, lv;
            split4(t, hv, lv);
            const uint32_t so = swz((uint32_t)(row * 128 + c16 * 8));
            *reinterpret_cast<uint2*>(smem + BUF + so)        = hv;
            *reinterpret_cast<uint2*>(smem + BUF + 8192 + so) = lv;
        }
    }
    __syncthreads();

    uint32_t qh[4][4], ql[4][4];
    #pragma unroll
    for (int ks = 0; ks < 4; ks++) {
        const uint32_t off = swz((uint32_t)(a_row * 128 + (2 * ks + a_ca) * 16));
        ldsm4(qh[ks][0], qh[ks][1], qh[ks][2], qh[ks][3], smu + BUF + off);
        ldsm4(ql[ks][0], ql[ks][1], ql[ks][2], ql[ks][3], smu + BUF + 8192 + off);
    }
    __syncthreads();

    // tile1 copy into buf1
    copy_tile(smu + BUF, tile_base0 + TILE_BYTES, tid);
    asm volatile("cp.async.commit_group;");

    float ofr[8][4];
    #pragma unroll
    for (int j = 0; j < 8; j++)
        #pragma unroll
        for (int e = 0; e < 4; e++) ofr[j][e] = 0.f;
    float mrow[2] = {-1e30f, -1e30f};   // log2-domain running max
    float lrow[2] = {0.f, 0.f};

    const int rr0 = q0 + 16 * w + (lane >> 2);
    const int cq  = (lane & 3) * 2;
    const unsigned long long* pm0 = gPM + (size_t)(b * S + rr0) * NTILES;
    const unsigned long long* pm1 = gPM + (size_t)(b * S + rr0 + 8) * NTILES;

    for (int it = 0; it < NTILES; it++) {
        const int k0 = it * TK;
        const uint32_t bufb = (uint32_t)(it & 1) * BUF;
        const uint32_t KHI = bufb, KLO = bufb + 8192, VHI = bufb + 16384;

        asm volatile("cp.async.wait_group 1;");
        __syncthreads();

        const unsigned long long mw[2] = {pm0[it], pm1[it]};
        float2 bfr0[4][2];
        #pragma unroll
        for (int j = 0; j < 4; j++)
            #pragma unroll
            for (int p = 0; p < 2; p++)
                bfr0[j][p] = *reinterpret_cast<const float2*>(
                    gbias + ((size_t)bh * S + rr0 + 8 * p) * S + k0 + 8 * j + cq);

        float sfr[8][4];
        #pragma unroll
        for (int j = 0; j < 8; j++)
            #pragma unroll
            for (int e = 0; e < 4; e++) sfr[j][e] = 0.f;

        // ---- QK keys 0..31 (bf16 3-term) ----
        #pragma unroll
        for (int ks = 0; ks < 4; ks++)
            #pragma unroll
            for (int i = 0; i < 2; i++) {
                const uint32_t off = swz((uint32_t)((16 * i + b_ro) * 128 + (2 * ks + b_ca) * 16));
                uint32_t kh0, kh1, kh2, kh3, kl0, kl1, kl2, kl3;
                ldsm4(kh0, kh1, kh2, kh3, smu + KHI + off);
                ldsm4(kl0, kl1, kl2, kl3, smu + KLO + off);
                mma_bf(sfr[2 * i],     qh[ks][0], qh[ks][1], qh[ks][2], qh[ks][3], kh0, kh1);
                mma_bf(sfr[2 * i],     qh[ks][0], qh[ks][1], qh[ks][2], qh[ks][3], kl0, kl1);
                mma_bf(sfr[2 * i],     ql[ks][0], ql[ks][1], ql[ks][2], ql[ks][3], kh0, kh1);
                mma_bf(sfr[2 * i + 1], qh[ks][0], qh[ks][1], qh[ks][2], qh[ks][3], kh2, kh3);
                mma_bf(sfr[2 * i + 1], qh[ks][0], qh[ks][1], qh[ks][2], qh[ks][3], kl2, kl3);
                mma_bf(sfr[2 * i + 1], ql[ks][0], ql[ks][1], ql[ks][2], ql[ks][3], kh2, kh3);
            }

        float2 bfr1[4][2];
        #pragma unroll
        for (int j = 0; j < 4; j++)
            #pragma unroll
            for (int p = 0; p < 2; p++)
                bfr1[j][p] = *reinterpret_cast<const float2*>(
                    gbias + ((size_t)bh * S + rr0 + 8 * p) * S + k0 + 32 + 8 * j + cq);

        // ---- QK keys 32..63 ----
        #pragma unroll
        for (int ks = 0; ks < 4; ks++)
            #pragma unroll
            for (int i = 2; i < 4; i++) {
                const uint32_t off = swz((uint32_t)((16 * i + b_ro) * 128 + (2 * ks + b_ca) * 16));
                uint32_t kh0, kh1, kh2, kh3, kl0, kl1, kl2, kl3;
                ldsm4(kh0, kh1, kh2, kh3, smu + KHI + off);
                ldsm4(kl0, kl1, kl2, kl3, smu + KLO + off);
                mma_bf(sfr[2 * i],     qh[ks][0], qh[ks][1], qh[ks][2], qh[ks][3], kh0, kh1);
                mma_bf(sfr[2 * i],     qh[ks][0], qh[ks][1], qh[ks][2], qh[ks][3], kl0, kl1);
                mma_bf(sfr[2 * i],     ql[ks][0], ql[ks][1], ql[ks][2], ql[ks][3], kh0, kh1);
                mma_bf(sfr[2 * i + 1], qh[ks][0], qh[ks][1], qh[ks][2], qh[ks][3], kh2, kh3);
                mma_bf(sfr[2 * i + 1], qh[ks][0], qh[ks][1], qh[ks][2], qh[ks][3], kl2, kl3);
                mma_bf(sfr[2 * i + 1], ql[ks][0], ql[ks][1], ql[ks][2], ql[ks][3], kh2, kh3);
            }

        // ---- bias (x log2e via FMA) + packed mask ----
        #pragma unroll
        for (int j = 0; j < 8; j++) {
            const float2* bp = (j < 4) ? bfr0[j] : bfr1[j - 4];
            const int base = 8 * j + cq;
            #pragma unroll
            for (int p = 0; p < 2; p++) {
                const unsigned mb = (unsigned)(mw[p] >> base);
                sfr[j][2 * p]     = (mb & 1u) ? 0.0f : fmaf(bp[p].x, LOG2E, sfr[j][2 * p]);
                sfr[j][2 * p + 1] = (mb & 2u) ? 0.0f : fmaf(bp[p].y, LOG2E, sfr[j][2 * p + 1]);
            }
        }

        // ---- single online softmax (log2 domain, EX2 only) ----
        float mold[2], mnew2[2], rs2[2];
        #pragma unroll
        for (int p = 0; p < 2; p++) {
            float mx = -1e30f;
            #pragma unroll
            for (int j = 0; j < 8; j++)
                mx = fmaxf(mx, fmaxf(sfr[j][2 * p], sfr[j][2 * p + 1]));
            mx = fmaxf(mx, __shfl_xor_sync(0xffffffffu, mx, 1));
            mx = fmaxf(mx, __shfl_xor_sync(0xffffffffu, mx, 2));
            mold[p] = mrow[p];
            const float mnew = fmaxf(mrow[p], mx);
            mrow[p] = mnew;
            mnew2[p] = mnew;

            float rs = 0.f;
            #pragma unroll
            for (int j = 0; j < 8; j++) {
                const float e0 = ex2(sfr[j][2 * p]     - mnew);
                const float e1 = ex2(sfr[j][2 * p + 1] - mnew);
                sfr[j][2 * p] = e0; sfr[j][2 * p + 1] = e1;
                rs += e0 + e1;
            }
            rs += __shfl_xor_sync(0xffffffffu, rs, 1);
            rs += __shfl_xor_sync(0xffffffffu, rs, 2);
            rs2[p] = rs;
        }

        // lazy rescale (warp-uniform skip)
        const bool moved = (mnew2[0] != mold[0]) || (mnew2[1] != mold[1]);
        if (__any_sync(0xffffffffu, moved)) {
            const float c0 = ex2(mold[0] - mnew2[0]);
            const float c1 = ex2(mold[1] - mnew2[1]);
            lrow[0] = lrow[0] * c0 + rs2[0];
            lrow[1] = lrow[1] * c1 + rs2[1];
            #pragma unroll
            for (int j = 0; j < 8; j++) {
                ofr[j][0] *= c0; ofr[j][1] *= c0;
                ofr[j][2] *= c1; ofr[j][3] *= c1;
            }
        } else {
            lrow[0] += rs2[0];
            lrow[1] += rs2[1];
        }

        // ---- PV: fp16 1-term (P single fp16, V single fp16) ----
        #pragma unroll
        for (int ksp = 0; ksp < 4; ksp++) {
            uint32_t ph[4];
            #pragma unroll
            for (int half = 0; half < 2; half++) {
                const int j = 2 * ksp + half;
                #pragma unroll
                for (int p = 0; p < 2; p++)
                    ph[half * 2 + p] = cvt_f16x2(sfr[j][2 * p + 1], sfr[j][2 * p]);
            }
            #pragma unroll
            for (int i = 0; i < 4; i++) {
                const uint32_t off = swz((uint32_t)((16 * ksp + v_ro) * 128 + (2 * i + v_ca) * 16));
                uint32_t vh0, vh1, vh2, vh3;
                ldsm4t(vh0, vh1, vh2, vh3, smu + VHI + off);
                mma_fp(ofr[2 * i],     ph[0], ph[1], ph[2], ph[3], vh0, vh1);
                mma_fp(ofr[2 * i + 1], ph[0], ph[1], ph[2], ph[3], vh2, vh3);
            }
        }

        __syncthreads();
        if (it + 2 < NTILES)
            copy_tile(smu + bufb, tile_base0 + (size_t)(it + 2) * TILE_BYTES, tid);
        asm volatile("cp.async.commit_group;");
    }

    // ---- epilogue ----
    const float inv0 = 1.0f / lrow[0];
    const float inv1 = 1.0f / lrow[1];
    #pragma unroll
    for (int j = 0; j < 8; j++) {
        const int d = 8 * j + cq;
        float2 w0 = make_float2(ofr[j][0] * inv0, ofr[j][1] * inv0);
        float2 w1 = make_float2(ofr[j][2] * inv1, ofr[j][3] * inv1);
        *reinterpret_cast<float2*>(gout + ((size_t)(b * S + rr0)     * H + h) * D + d) = w0;
        *reinterpret_cast<float2*>(gout + ((size_t)(b * S + rr0 + 8) * H + h) * D + d) = w1;
    }
}

extern "C" void kernel_launch(void* const* d_in, const int* in_sizes, int n_in,
                              void* d_out, int out_size) {
    const float* q    = (const float*)d_in[0];
    const float* k    = (const float*)d_in[1];
    const float* v    = (const float*)d_in[2];
    const float* bias = (const float*)d_in[3];
    const int*   mask = (const int*)d_in[4];
    float* out = (float*)d_out;

    prepass_kernel<<<SPLIT_BLOCKS + MASK_BLOCKS, 256>>>(k, v, mask);

    cudaFuncSetAttribute(attn_mma_kernel,
                         cudaFuncAttributeMaxDynamicSharedMemorySize, SMEM_BYTES);
    dim3 grid(B * H, S / TQ);
    attn_mma_kernel<<<grid, NT, SMEM_BYTES>>>(q, bias, out);
}